// round 13
// baseline (speedup 1.0000x reference)
#include <cuda_runtime.h>
#include <math.h>

#define NB 16
#define NA 5
#define NH 96
#define NW 96
#define NHW 9216
#define TT 50
#define ROWS 16
#define TPB 384                          // 4 thread-rows x 96; 4 cells/thread
#define ROWGRP (NH / ROWS)               // 6
#define DENSE_BX (NA * ROWGRP)           // 30 dense blocks per batch
#define N_PART (DENSE_BX * NB)           // 480

__constant__ float c_aw[NA] = {1.3221f, 3.19275f, 5.05587f, 9.47112f, 11.2364f};
__constant__ float c_ah[NA] = {1.73145f, 4.00944f, 8.09892f, 4.84053f, 10.0071f};

__device__ float4 g_tA[NB * TT];     // gt extents: xlo, xhi, ylo, yhi
__device__ float  g_bz[NB * TT];     // 0.6 * gt area
__device__ int    g_nv[NB];
__device__ float4 g_m0[NB * TT];     // gx, gy, gw, gh
__device__ float  g_lr[NB * TT];
__device__ int4   g_meta[NB * TT];   // idx(within batch), bn, owner, cls
__device__ double g_sparse[NB];
__device__ double g_part[N_PART];

__device__ __forceinline__ float sigmoidf_(float x) { return 1.f / (1.f + __expf(-x)); }

// ---------------------------------------------------------------------------
// Kernel 0 (R12 verbatim): target parsing, anchor argmax, ownership.
// ONE block, 800 threads.
// ---------------------------------------------------------------------------
__global__ void __launch_bounds__(NB * TT)
box_prep(const float* __restrict__ tgt)
{
    __shared__ int   s_nv[NB];
    __shared__ int   sidx[NB * TT];
    __shared__ float s_t[NB * TT * 6];     // 19.2 KB

    const int tid = threadIdx.x;      // 0..799
    const int b = tid / TT;
    const int t = tid - b * TT;

    // coalesced staging: 4800 floats = 1200 float4, 2 rounds over 800 threads
    {
        const float4* src = reinterpret_cast<const float4*>(tgt);
        float4* dst = reinterpret_cast<float4*>(s_t);
        dst[tid] = src[tid];
        if (tid < NB * TT * 6 / 4 - NB * TT)
            dst[NB * TT + tid] = src[NB * TT + tid];
    }
    if (tid < NB) s_nv[tid] = TT;
    __syncthreads();

    const float* tp = s_t + tid * 6;
    const float tcls = tp[0];
    const float xr = tp[1];
    const float gx = xr * NW;
    const float gy = tp[2] * NH;
    const float gw = tp[3] * NW;
    const float gh = tp[4] * NH;
    const float lr = tp[5];

    if (xr == 0.f) atomicMin(&s_nv[b], t);   // native int ATOMS

    // best anchor (first-index-wins, matching jnp.argmax)
    const float area = gw * gh;
    int bn = 0;
    float best = -1.f;
#pragma unroll
    for (int k = 0; k < NA; k++) {
        const float inter = fminf(gw, c_aw[k]) * fminf(gh, c_ah[k]);
        const float iou = inter / (area + c_aw[k] * c_ah[k] - inter);
        if (iou > best) { best = iou; bn = k; }
    }
    const int gi = (int)gx;
    const int gj = (int)gy;
    const int idx = bn * NHW + gj * NW + gi;
    sidx[tid] = idx;
    __syncthreads();

    const int nv = s_nv[b];
    const bool valid = t < nv;

    // last-valid-write-wins ownership, branch-free accumulate
    int dup = 0;
    for (int t2 = t + 1; t2 < nv; t2++)
        dup |= (sidx[b * TT + t2] == idx);
    const bool owner = valid && !dup;

    g_tA[tid] = make_float4(gx - 0.5f * gw, gx + 0.5f * gw,
                            gy - 0.5f * gh, gy + 0.5f * gh);
    g_bz[tid] = 0.6f * area;
    g_m0[tid] = make_float4(gx, gy, gw, gh);
    g_lr[tid] = lr;
    g_meta[tid] = make_int4(idx, bn, owner ? 1 : 0, (int)tcls);
    if (t == 0) g_nv[b] = nv;
}

// ---------------------------------------------------------------------------
// Kernel 1: dense no-object term + sparse per-target loss.
// grid = (31, 16), block = 384. Each dense block covers 16 rows of one anchor;
// each thread processes FOUR cells (rows j, j+4, j+8, j+12).
//   blockIdx.x < 30 : dense, y-band pruned (tight band: py in (gylo,gyhi)).
//   blockIdx.x == 30: sparse loss for batch blockIdx.y.
// ---------------------------------------------------------------------------
__global__ void __launch_bounds__(TPB)
dense_kernel(const float* __restrict__ out)
{
    __shared__ float4 sA[TT + 2];
    __shared__ float  sbz[TT + 2];
    __shared__ int    smask[2];
    __shared__ int    s_nv;
    __shared__ float  wsum[TPB / 32];
    __shared__ double wsumd[TPB / 32];

    const int b = blockIdx.y;
    const int bx = blockIdx.x;
    const int tid = threadIdx.x;

    if (bx == DENSE_BX) {
        // =================== SPARSE PATH (R12 verbatim) ===================
        if (tid == 0) s_nv = g_nv[b];
        if (tid < TT) {
            sA[tid] = g_tA[b * TT + tid];
            sbz[tid] = g_bz[b * TT + tid];
        }
        __syncthreads();
        const int nv = s_nv;

        double c = 0.0;
        if (tid < TT) {
            const int4 meta = g_meta[b * TT + tid];
            if (meta.z) {
                const int idx = meta.x, bn = meta.y, cls = meta.w;
                const int hw = idx - bn * NHW;
                const int gj = hw / NW;
                const int gi = hw - gj * NW;
                const float4 m0 = g_m0[b * TT + tid];
                const float gx = m0.x, gy = m0.y, gw = m0.z, gh = m0.w;
                const float lr = g_lr[b * TT + tid];

                const float* op = out + ((b * NA + bn) * 8) * NHW + hw;
                const float o0 = op[0];
                const float o1 = op[NHW];
                const float o2 = op[2 * NHW];
                const float o3 = op[3 * NHW];
                const float o4 = op[4 * NHW];
                const float o5 = op[5 * NHW];
                const float o6 = op[6 * NHW];
                const float o7 = op[7 * NHW];

                const float x = sigmoidf_(o0);
                const float y = sigmoidf_(o1);
                const float px = x + (float)gi;
                const float py = y + (float)gj;
                const float pw = __expf(o2) * c_aw[bn];
                const float ph = __expf(o3) * c_ah[bn];

                const float tx = gx - (float)gi;
                const float ty = gy - (float)gj;
                const float tw = __logf(gw / c_aw[bn]);
                const float th = __logf(gh / c_ah[bn]);

                const float xlo = px - 0.5f * pw, xhi = px + 0.5f * pw;
                const float ylo = py - 0.5f * ph, yhi = py + 0.5f * ph;

                // tconf = IoU(gt, pred_at)
                const float iw = fminf(gx + 0.5f * gw, xhi) - fmaxf(gx - 0.5f * gw, xlo);
                const float ih = fminf(gy + 0.5f * gh, yhi) - fmaxf(gy - 0.5f * gh, ylo);
                const float ca = (iw > 0.f && ih > 0.f) ? iw * ih : 0.f;
                const float tconf = ca / (gw * gh + pw * ph - ca);

                const float conf = sigmoidf_(o4);

                // over predicate — IDENTICAL branch-free expression to dense path
                const float c1 = 0.6f * (pw * ph);
                float bestm = -1.f;
                for (int k = 0; k < nv; k++) {
                    const float4 a4 = sA[k];
                    const float iw2 = fminf(xhi, a4.y) - fmaxf(xlo, a4.x);
                    const float ih2 = fminf(yhi, a4.w) - fmaxf(ylo, a4.z);
                    const float hit = fminf(fminf(iw2, ih2),
                                            fmaf(1.6f, iw2 * ih2, -sbz[k]) - c1);
                    bestm = fmaxf(bestm, hit);
                }
                const bool over = bestm > 0.f;

                const float dx = x - tx;   c += 0.5 * (double)(dx * dx);
                const float dy = y - ty;   c += 0.5 * (double)(dy * dy);
                const float dw = o2 - tw;  c += 0.5 * (double)(dw * dw);
                const float dh = o3 - th;  c += 0.5 * (double)(dh * dh);
                const float dc = conf - tconf;
                c += 2.5 * (double)(dc * dc);                 // 0.5 * OBJECT_SCALE
                if (!over) c -= (double)(0.5f * conf * conf); // cancel dense term

                const float m = fmaxf(o5, o6);
                const float lse = m + __logf(__expf(o5 - m) + __expf(o6 - m));
                c += (double)(lse - (cls == 0 ? o5 : o6));

                const float clr = sigmoidf_(o7);
                const float dl = clr - lr;
                c += 0.25 * (double)(dl * dl);
            }
        }
#pragma unroll
        for (int off = 16; off > 0; off >>= 1)
            c += __shfl_down_sync(0xffffffffu, c, off);
        if ((tid & 31) == 0) wsumd[tid >> 5] = c;
        __syncthreads();
        if (tid == 0) {
            double s = 0.0;
#pragma unroll
            for (int k = 0; k < TPB / 32; k++) s += wsumd[k];
            g_sparse[b] = s;
        }
        return;
    }

    // =================== DENSE PATH: 4 cells per thread ===================
    const int a = bx / ROWGRP;
    const int j0 = (bx - a * ROWGRP) * ROWS;
    const int jr = tid / NW;          // 0..3
    const int i = tid - jr * NW;

    // issue all four cells' output loads early (20 independent LDGs)
    const float* base = out + ((b * NA + a) * 8) * NHW + i;
    float o0[4], o1[4], o2[4], o3[4], o4[4];
#pragma unroll
    for (int q = 0; q < 4; q++) {
        const float* op = base + (j0 + jr + 4 * q) * NW;
        o0[q] = op[0];
        o1[q] = op[NHW];
        o2[q] = op[2 * NHW];
        o3[q] = op[3 * NHW];
        o4[q] = op[4 * NHW];
    }

    if (tid == 0) s_nv = g_nv[b];

    // coalesced load of precomputed boxes + tight band prune + ballot compaction
    float4 ext; float bz = 0.f;
    bool keep = false;
    if (tid < TT) {
        ext = g_tA[b * TT + tid];
        bz = g_bz[b * TT + tid];
        // tight band (proof in R11): hit requires py strictly in (gylo, gyhi)
        keep = ((float)j0 < ext.w + 0.125f) && ((float)(j0 + ROWS) > ext.z - 0.125f);
    }
    __syncthreads();                      // s_nv visible
    if (tid < 64) {
        keep = keep && (tid < s_nv);
        unsigned m = __ballot_sync(0xffffffffu, keep);
        if ((tid & 31) == 0) smask[tid >> 5] = (int)m;
    }
    __syncthreads();
    const unsigned m0 = (unsigned)smask[0];
    const unsigned m1 = (unsigned)smask[1];
    const int cnt = __popc(m0) + __popc(m1);
    if (keep) {
        const unsigned below = (tid < 32) ? (m0 & ((1u << tid) - 1u))
                                          : m1 & ((tid == 32) ? 0u : ((1u << (tid - 32)) - 1u));
        const int pos = ((tid < 32) ? 0 : __popc(m0)) + __popc(below);
        sA[pos] = ext;
        sbz[pos] = bz;
    }
    if (tid < 2) {   // never-firing pad so the chunk-2 loop needs no tail
        sA[cnt + tid] = make_float4(1e30f, -1e30f, 1e30f, -1e30f);
        sbz[cnt + tid] = 0.f;
    }
    __syncthreads();

    // per-cell boxes
    float xlo[4], xhi[4], ylo[4], yhi[4], c1[4], bestq[4];
#pragma unroll
    for (int q = 0; q < 4; q++) {
        const int j = j0 + jr + 4 * q;
        const float px = sigmoidf_(o0[q]) + (float)i;
        const float py = sigmoidf_(o1[q]) + (float)j;
        const float pw = __expf(o2[q]) * c_aw[a];
        const float ph = __expf(o3[q]) * c_ah[a];
        xlo[q] = px - 0.5f * pw; xhi[q] = px + 0.5f * pw;
        ylo[q] = py - 0.5f * ph; yhi[q] = py + 0.5f * ph;
        c1[q] = 0.6f * (pw * ph);
        bestq[q] = -1.f;
    }

    // branch-free inner loop, 4 independent chains, unroll-by-2 (8-way ILP)
    for (int k = 0; k < cnt; k += 2) {
#pragma unroll
        for (int u = 0; u < 2; u++) {
            const float4 a4 = sA[k + u];
            const float z = sbz[k + u];
#pragma unroll
            for (int q = 0; q < 4; q++) {
                const float iw = fminf(xhi[q], a4.y) - fmaxf(xlo[q], a4.x);
                const float ih = fminf(yhi[q], a4.w) - fmaxf(ylo[q], a4.z);
                bestq[q] = fmaxf(bestq[q], fminf(fminf(iw, ih),
                                 fmaf(1.6f, iw * ih, -z) - c1[q]));
            }
        }
    }

    float term = 0.f;
#pragma unroll
    for (int q = 0; q < 4; q++) {
        const float conf = sigmoidf_(o4[q]);
        term += (bestq[q] > 0.f) ? 0.f : 0.5f * conf * conf;
    }

#pragma unroll
    for (int off = 16; off > 0; off >>= 1)
        term += __shfl_down_sync(0xffffffffu, term, off);
    if ((tid & 31) == 0) wsum[tid >> 5] = term;
    __syncthreads();
    if (tid == 0) {
        float s = 0.f;
#pragma unroll
        for (int k = 0; k < TPB / 32; k++) s += wsum[k];
        g_part[b * DENSE_BX + bx] = (double)s;   // plain store, no atomic
    }
}

// ---------------------------------------------------------------------------
// Kernel 2: sum 480 partials + 16 sparse sums -> scalar.
// ---------------------------------------------------------------------------
__global__ void __launch_bounds__(256)
finalize_kernel(float* __restrict__ res)
{
    __shared__ double wsumd[8];
    const int tid = threadIdx.x;
    double s = 0.0;
    for (int k = tid; k < N_PART; k += 256) s += g_part[k];
    if (tid < NB) s += g_sparse[tid];
#pragma unroll
    for (int off = 16; off > 0; off >>= 1)
        s += __shfl_down_sync(0xffffffffu, s, off);
    if ((tid & 31) == 0) wsumd[tid >> 5] = s;
    __syncthreads();
    if (tid == 0) {
        double t = 0.0;
#pragma unroll
        for (int k = 0; k < 8; k++) t += wsumd[k];
        res[0] = (float)(t / (double)NB);
    }
}

extern "C" void kernel_launch(void* const* d_in, const int* in_sizes, int n_in,
                              void* d_out, int out_size)
{
    const float* output = (const float*)d_in[0];
    const float* target = (const float*)d_in[1];
    float* res = (float*)d_out;

    box_prep<<<1, NB * TT>>>(target);
    dense_kernel<<<dim3(DENSE_BX + 1, NB), TPB>>>(output);
    finalize_kernel<<<1, 256>>>(res);
}

// round 14
// speedup vs baseline: 1.0769x; 1.0769x over previous
#include <cuda_runtime.h>
#include <math.h>

#define NB 16
#define NA 5
#define NH 96
#define NW 96
#define NHW 9216
#define TT 50
#define ROWS 8
#define TPB 384                          // 4 thread-rows x 96; 2 cells/thread
#define ROWGRP (NH / ROWS)               // 12
#define DENSE_BX (NA * ROWGRP)           // 60 dense blocks per batch
#define N_PART (DENSE_BX * NB)           // 960

__constant__ float c_aw[NA] = {1.3221f, 3.19275f, 5.05587f, 9.47112f, 11.2364f};
__constant__ float c_ah[NA] = {1.73145f, 4.00944f, 8.09892f, 4.84053f, 10.0071f};

__device__ float4 g_tA[NB * TT];     // gt extents: xlo, xhi, ylo, yhi
__device__ float  g_bz[NB * TT];     // 0.6 * gt area
__device__ int    g_nv[NB];
__device__ float4 g_m0[NB * TT];     // gx, gy, gw, gh
__device__ float  g_lr[NB * TT];
__device__ int4   g_meta[NB * TT];   // idx(within batch), bn, owner, cls
__device__ double g_sparse[NB];
__device__ double g_part[N_PART];

__device__ __forceinline__ float sigmoidf_(float x) { return 1.f / (1.f + __expf(-x)); }

// ---------------------------------------------------------------------------
// Kernel 0 (R12 verbatim): target parsing, anchor argmax, ownership.
// ONE block, 800 threads.
// ---------------------------------------------------------------------------
__global__ void __launch_bounds__(NB * TT)
box_prep(const float* __restrict__ tgt)
{
    __shared__ int   s_nv[NB];
    __shared__ int   sidx[NB * TT];
    __shared__ float s_t[NB * TT * 6];     // 19.2 KB

    const int tid = threadIdx.x;      // 0..799
    const int b = tid / TT;
    const int t = tid - b * TT;

    // coalesced staging: 4800 floats = 1200 float4, 2 rounds over 800 threads
    {
        const float4* src = reinterpret_cast<const float4*>(tgt);
        float4* dst = reinterpret_cast<float4*>(s_t);
        dst[tid] = src[tid];
        if (tid < NB * TT * 6 / 4 - NB * TT)
            dst[NB * TT + tid] = src[NB * TT + tid];
    }
    if (tid < NB) s_nv[tid] = TT;
    __syncthreads();

    const float* tp = s_t + tid * 6;
    const float tcls = tp[0];
    const float xr = tp[1];
    const float gx = xr * NW;
    const float gy = tp[2] * NH;
    const float gw = tp[3] * NW;
    const float gh = tp[4] * NH;
    const float lr = tp[5];

    if (xr == 0.f) atomicMin(&s_nv[b], t);   // native int ATOMS

    // best anchor (first-index-wins, matching jnp.argmax)
    const float area = gw * gh;
    int bn = 0;
    float best = -1.f;
#pragma unroll
    for (int k = 0; k < NA; k++) {
        const float inter = fminf(gw, c_aw[k]) * fminf(gh, c_ah[k]);
        const float iou = inter / (area + c_aw[k] * c_ah[k] - inter);
        if (iou > best) { best = iou; bn = k; }
    }
    const int gi = (int)gx;
    const int gj = (int)gy;
    const int idx = bn * NHW + gj * NW + gi;
    sidx[tid] = idx;
    __syncthreads();

    const int nv = s_nv[b];
    const bool valid = t < nv;

    // last-valid-write-wins ownership, branch-free accumulate
    int dup = 0;
    for (int t2 = t + 1; t2 < nv; t2++)
        dup |= (sidx[b * TT + t2] == idx);
    const bool owner = valid && !dup;

    g_tA[tid] = make_float4(gx - 0.5f * gw, gx + 0.5f * gw,
                            gy - 0.5f * gh, gy + 0.5f * gh);
    g_bz[tid] = 0.6f * area;
    g_m0[tid] = make_float4(gx, gy, gw, gh);
    g_lr[tid] = lr;
    g_meta[tid] = make_int4(idx, bn, owner ? 1 : 0, (int)tcls);
    if (t == 0) g_nv[b] = nv;
}

// ---------------------------------------------------------------------------
// Kernel 1 (R12 logic + PDL): dense no-object term + sparse per-target loss.
// Launched with programmatic stream serialization: all work independent of
// box_prep output (out loads + per-cell box math) runs BEFORE
// cudaGridDependencySynchronize(), overlapping box_prep.
// ---------------------------------------------------------------------------
__global__ void __launch_bounds__(TPB)
dense_kernel(const float* __restrict__ out)
{
    __shared__ float4 sA[TT + 4];
    __shared__ float  sbz[TT + 4];
    __shared__ int    smask[2];
    __shared__ int    s_nv;
    __shared__ float  wsum[TPB / 32];
    __shared__ double wsumd[TPB / 32];

    const int b = blockIdx.y;
    const int bx = blockIdx.x;
    const int tid = threadIdx.x;

    if (bx == DENSE_BX) {
        // =================== SPARSE PATH ===================
        cudaGridDependencySynchronize();      // wait for box_prep results
        if (tid == 0) s_nv = g_nv[b];
        if (tid < TT) {
            sA[tid] = g_tA[b * TT + tid];
            sbz[tid] = g_bz[b * TT + tid];
        }
        __syncthreads();
        const int nv = s_nv;

        double c = 0.0;
        if (tid < TT) {
            const int4 meta = g_meta[b * TT + tid];
            if (meta.z) {
                const int idx = meta.x, bn = meta.y, cls = meta.w;
                const int hw = idx - bn * NHW;
                const int gj = hw / NW;
                const int gi = hw - gj * NW;
                const float4 m0 = g_m0[b * TT + tid];
                const float gx = m0.x, gy = m0.y, gw = m0.z, gh = m0.w;
                const float lr = g_lr[b * TT + tid];

                const float* op = out + ((b * NA + bn) * 8) * NHW + hw;
                const float o0 = op[0];
                const float o1 = op[NHW];
                const float o2 = op[2 * NHW];
                const float o3 = op[3 * NHW];
                const float o4 = op[4 * NHW];
                const float o5 = op[5 * NHW];
                const float o6 = op[6 * NHW];
                const float o7 = op[7 * NHW];

                const float x = sigmoidf_(o0);
                const float y = sigmoidf_(o1);
                const float px = x + (float)gi;
                const float py = y + (float)gj;
                const float pw = __expf(o2) * c_aw[bn];
                const float ph = __expf(o3) * c_ah[bn];

                const float tx = gx - (float)gi;
                const float ty = gy - (float)gj;
                const float tw = __logf(gw / c_aw[bn]);
                const float th = __logf(gh / c_ah[bn]);

                const float xlo = px - 0.5f * pw, xhi = px + 0.5f * pw;
                const float ylo = py - 0.5f * ph, yhi = py + 0.5f * ph;

                // tconf = IoU(gt, pred_at)
                const float iw = fminf(gx + 0.5f * gw, xhi) - fmaxf(gx - 0.5f * gw, xlo);
                const float ih = fminf(gy + 0.5f * gh, yhi) - fmaxf(gy - 0.5f * gh, ylo);
                const float ca = (iw > 0.f && ih > 0.f) ? iw * ih : 0.f;
                const float tconf = ca / (gw * gh + pw * ph - ca);

                const float conf = sigmoidf_(o4);

                // over predicate — IDENTICAL branch-free expression to dense path
                const float c1 = 0.6f * (pw * ph);
                float bestm = -1.f;
                for (int k = 0; k < nv; k++) {
                    const float4 a4 = sA[k];
                    const float iw2 = fminf(xhi, a4.y) - fmaxf(xlo, a4.x);
                    const float ih2 = fminf(yhi, a4.w) - fmaxf(ylo, a4.z);
                    const float hit = fminf(fminf(iw2, ih2),
                                            fmaf(1.6f, iw2 * ih2, -sbz[k]) - c1);
                    bestm = fmaxf(bestm, hit);
                }
                const bool over = bestm > 0.f;

                const float dx = x - tx;   c += 0.5 * (double)(dx * dx);
                const float dy = y - ty;   c += 0.5 * (double)(dy * dy);
                const float dw = o2 - tw;  c += 0.5 * (double)(dw * dw);
                const float dh = o3 - th;  c += 0.5 * (double)(dh * dh);
                const float dc = conf - tconf;
                c += 2.5 * (double)(dc * dc);                 // 0.5 * OBJECT_SCALE
                if (!over) c -= (double)(0.5f * conf * conf); // cancel dense term

                const float m = fmaxf(o5, o6);
                const float lse = m + __logf(__expf(o5 - m) + __expf(o6 - m));
                c += (double)(lse - (cls == 0 ? o5 : o6));

                const float clr = sigmoidf_(o7);
                const float dl = clr - lr;
                c += 0.25 * (double)(dl * dl);
            }
        }
#pragma unroll
        for (int off = 16; off > 0; off >>= 1)
            c += __shfl_down_sync(0xffffffffu, c, off);
        if ((tid & 31) == 0) wsumd[tid >> 5] = c;
        __syncthreads();
        if (tid == 0) {
            double s = 0.0;
#pragma unroll
            for (int k = 0; k < TPB / 32; k++) s += wsumd[k];
            g_sparse[b] = s;
        }
        return;
    }

    // =================== DENSE PATH: 2 cells per thread ===================
    const int a = bx / ROWGRP;
    const int j0 = (bx - a * ROWGRP) * ROWS;
    const int jr = tid / NW;          // 0..3
    const int i = tid - jr * NW;
    const int jA = j0 + jr;
    const int jB = j0 + jr + 4;

    // ---- pre-sync phase: everything independent of box_prep ----
    const float* base = out + ((b * NA + a) * 8) * NHW + i;
    const float* opA = base + jA * NW;
    const float* opB = base + jB * NW;
    const float a0 = opA[0];
    const float a1 = opA[NHW];
    const float a2 = opA[2 * NHW];
    const float a3 = opA[3 * NHW];
    const float a4v = opA[4 * NHW];
    const float b0 = opB[0];
    const float b1 = opB[NHW];
    const float b2 = opB[2 * NHW];
    const float b3 = opB[3 * NHW];
    const float b4v = opB[4 * NHW];

    // per-cell boxes (pure math on loaded values — still pre-sync)
    const float pxA = sigmoidf_(a0) + (float)i;
    const float pyA = sigmoidf_(a1) + (float)jA;
    const float pwA = __expf(a2) * c_aw[a];
    const float phA = __expf(a3) * c_ah[a];
    const float xloA = pxA - 0.5f * pwA, xhiA = pxA + 0.5f * pwA;
    const float yloA = pyA - 0.5f * phA, yhiA = pyA + 0.5f * phA;
    const float c1A = 0.6f * (pwA * phA);
    const float pxB = sigmoidf_(b0) + (float)i;
    const float pyB = sigmoidf_(b1) + (float)jB;
    const float pwB = __expf(b2) * c_aw[a];
    const float phB = __expf(b3) * c_ah[a];
    const float xloB = pxB - 0.5f * pwB, xhiB = pxB + 0.5f * pwB;
    const float yloB = pyB - 0.5f * phB, yhiB = pyB + 0.5f * phB;
    const float c1B = 0.6f * (pwB * phB);
    const float confA = sigmoidf_(a4v);
    const float confB = sigmoidf_(b4v);

    // ---- wait for box_prep output ----
    cudaGridDependencySynchronize();

    if (tid == 0) s_nv = g_nv[b];

    // coalesced load of precomputed boxes + tight band prune + ballot compaction
    float4 ext; float bz = 0.f;
    bool keep = false;
    if (tid < TT) {
        ext = g_tA[b * TT + tid];
        bz = g_bz[b * TT + tid];
        // tight band (proof in R11): hit requires py strictly in (gylo, gyhi)
        keep = ((float)j0 < ext.w + 0.125f) && ((float)(j0 + ROWS) > ext.z - 0.125f);
    }
    __syncthreads();                      // s_nv visible
    if (tid < 64) {
        keep = keep && (tid < s_nv);
        unsigned m = __ballot_sync(0xffffffffu, keep);
        if ((tid & 31) == 0) smask[tid >> 5] = (int)m;
    }
    __syncthreads();
    const unsigned m0 = (unsigned)smask[0];
    const unsigned m1 = (unsigned)smask[1];
    const int cnt = __popc(m0) + __popc(m1);
    if (keep) {
        const unsigned below = (tid < 32) ? (m0 & ((1u << tid) - 1u))
                                          : m1 & ((tid == 32) ? 0u : ((1u << (tid - 32)) - 1u));
        const int pos = ((tid < 32) ? 0 : __popc(m0)) + __popc(below);
        sA[pos] = ext;
        sbz[pos] = bz;
    }
    if (tid < 4) {   // never-firing pad so the chunk-4 loop needs no tail
        sA[cnt + tid] = make_float4(1e30f, -1e30f, 1e30f, -1e30f);
        sbz[cnt + tid] = 0.f;
    }
    __syncthreads();

    // branch-free inner loop, two independent accumulation chains
    float bestA = -1.f, bestB = -1.f;
    for (int k = 0; k < cnt; k += 4) {
#pragma unroll
        for (int u = 0; u < 4; u++) {
            const float4 a4 = sA[k + u];
            const float z = sbz[k + u];
            const float iwA = fminf(xhiA, a4.y) - fmaxf(xloA, a4.x);
            const float ihA = fminf(yhiA, a4.w) - fmaxf(yloA, a4.z);
            bestA = fmaxf(bestA, fminf(fminf(iwA, ihA),
                                       fmaf(1.6f, iwA * ihA, -z) - c1A));
            const float iwB = fminf(xhiB, a4.y) - fmaxf(xloB, a4.x);
            const float ihB = fminf(yhiB, a4.w) - fmaxf(yloB, a4.z);
            bestB = fmaxf(bestB, fminf(fminf(iwB, ihB),
                                       fmaf(1.6f, iwB * ihB, -z) - c1B));
        }
    }

    float term = (bestA > 0.f ? 0.f : 0.5f * confA * confA)
               + (bestB > 0.f ? 0.f : 0.5f * confB * confB);

#pragma unroll
    for (int off = 16; off > 0; off >>= 1)
        term += __shfl_down_sync(0xffffffffu, term, off);
    if ((tid & 31) == 0) wsum[tid >> 5] = term;
    __syncthreads();
    if (tid == 0) {
        float s = 0.f;
#pragma unroll
        for (int k = 0; k < TPB / 32; k++) s += wsum[k];
        g_part[b * DENSE_BX + bx] = (double)s;   // plain store, no atomic
    }
}

// ---------------------------------------------------------------------------
// Kernel 2 (+PDL): sum 960 partials + 16 sparse sums -> scalar.
// ---------------------------------------------------------------------------
__global__ void __launch_bounds__(256)
finalize_kernel(float* __restrict__ res)
{
    __shared__ double wsumd[8];
    cudaGridDependencySynchronize();      // wait for dense_kernel results
    const int tid = threadIdx.x;
    double s = 0.0;
    for (int k = tid; k < N_PART; k += 256) s += g_part[k];
    if (tid < NB) s += g_sparse[tid];
#pragma unroll
    for (int off = 16; off > 0; off >>= 1)
        s += __shfl_down_sync(0xffffffffu, s, off);
    if ((tid & 31) == 0) wsumd[tid >> 5] = s;
    __syncthreads();
    if (tid == 0) {
        double t = 0.0;
#pragma unroll
        for (int k = 0; k < 8; k++) t += wsumd[k];
        res[0] = (float)(t / (double)NB);
    }
}

extern "C" void kernel_launch(void* const* d_in, const int* in_sizes, int n_in,
                              void* d_out, int out_size)
{
    const float* output = (const float*)d_in[0];
    const float* target = (const float*)d_in[1];
    float* res = (float*)d_out;

    box_prep<<<1, NB * TT>>>(target);

    cudaLaunchAttribute attrs[1];
    attrs[0].id = cudaLaunchAttributeProgrammaticStreamSerialization;
    attrs[0].val.programmaticStreamSerializationAllowed = 1;

    {
        cudaLaunchConfig_t cfg = {};
        cfg.gridDim = dim3(DENSE_BX + 1, NB);
        cfg.blockDim = dim3(TPB);
        cfg.dynamicSmemBytes = 0;
        cfg.stream = 0;                  // legacy default stream (captured)
        cfg.attrs = attrs;
        cfg.numAttrs = 1;
        cudaLaunchKernelEx(&cfg, dense_kernel, output);
    }
    {
        cudaLaunchConfig_t cfg = {};
        cfg.gridDim = dim3(1);
        cfg.blockDim = dim3(256);
        cfg.dynamicSmemBytes = 0;
        cfg.stream = 0;
        cfg.attrs = attrs;
        cfg.numAttrs = 1;
        cudaLaunchKernelEx(&cfg, finalize_kernel, res);
    }
}

// round 16
// speedup vs baseline: 1.1825x; 1.0980x over previous
#include <cuda_runtime.h>
#include <math.h>

#define NB 16
#define NA 5
#define NH 96
#define NW 96
#define NHW 9216
#define TT 50
#define ROWS 8
#define TPB 384                          // 4 thread-rows x 96; 2 cells/thread
#define ROWGRP (NH / ROWS)               // 12
#define DENSE_BX (NA * ROWGRP)           // 60 dense blocks per batch
#define TOTAL_BLOCKS ((DENSE_BX + 1) * NB)   // 976

__constant__ float c_aw[NA] = {1.3221f, 3.19275f, 5.05587f, 9.47112f, 11.2364f};
__constant__ float c_ah[NA] = {1.73145f, 4.00944f, 8.09892f, 4.84053f, 10.0071f};

__device__ float4 g_tA[NB * TT];     // gt extents: xlo, xhi, ylo, yhi
__device__ float  g_bz[NB * TT];     // 0.6 * gt area
__device__ int    g_nv[NB];
__device__ float4 g_m0[NB * TT];     // gx, gy, gw, gh
__device__ float  g_lr[NB * TT];
__device__ int4   g_meta[NB * TT];   // idx(within batch), bn, owner, cls
__device__ double g_acc;
__device__ unsigned g_done;

__device__ __forceinline__ float sigmoidf_(float x) { return 1.f / (1.f + __expf(-x)); }

// fence-free block-total accumulation: release-REDG + acq_rel counter.
// No membar.gl / CCTL.IVALL anywhere.
__device__ __forceinline__ void accumulate_and_maybe_finalize(double c, float* res)
{
    asm volatile("red.release.gpu.global.add.f64 [%0], %1;"
                 :: "l"(&g_acc), "d"(c) : "memory");
    unsigned old;
    asm volatile("atom.acq_rel.gpu.global.add.u32 %0, [%1], 1;"
                 : "=r"(old) : "l"(&g_done) : "memory");
    if (old == TOTAL_BLOCKS - 1) {
        double v;
        asm volatile("ld.acquire.gpu.global.f64 %0, [%1];"
                     : "=d"(v) : "l"(&g_acc) : "memory");
        res[0] = (float)(v / (double)NB);
    }
}

// ---------------------------------------------------------------------------
// Kernel 0 (R12 + accumulator reset): target parsing, anchor argmax, ownership.
// ONE block, 800 threads.
// ---------------------------------------------------------------------------
__global__ void __launch_bounds__(NB * TT)
box_prep(const float* __restrict__ tgt)
{
    __shared__ int   s_nv[NB];
    __shared__ int   sidx[NB * TT];
    __shared__ float s_t[NB * TT * 6];     // 19.2 KB

    const int tid = threadIdx.x;      // 0..799
    const int b = tid / TT;
    const int t = tid - b * TT;

    if (tid == 0) { g_acc = 0.0; g_done = 0u; }   // reset for this replay

    // coalesced staging: 4800 floats = 1200 float4, 2 rounds over 800 threads
    {
        const float4* src = reinterpret_cast<const float4*>(tgt);
        float4* dst = reinterpret_cast<float4*>(s_t);
        dst[tid] = src[tid];
        if (tid < NB * TT * 6 / 4 - NB * TT)
            dst[NB * TT + tid] = src[NB * TT + tid];
    }
    if (tid < NB) s_nv[tid] = TT;
    __syncthreads();

    const float* tp = s_t + tid * 6;
    const float tcls = tp[0];
    const float xr = tp[1];
    const float gx = xr * NW;
    const float gy = tp[2] * NH;
    const float gw = tp[3] * NW;
    const float gh = tp[4] * NH;
    const float lr = tp[5];

    if (xr == 0.f) atomicMin(&s_nv[b], t);   // native int ATOMS

    // best anchor (first-index-wins, matching jnp.argmax)
    const float area = gw * gh;
    int bn = 0;
    float best = -1.f;
#pragma unroll
    for (int k = 0; k < NA; k++) {
        const float inter = fminf(gw, c_aw[k]) * fminf(gh, c_ah[k]);
        const float iou = inter / (area + c_aw[k] * c_ah[k] - inter);
        if (iou > best) { best = iou; bn = k; }
    }
    const int gi = (int)gx;
    const int gj = (int)gy;
    const int idx = bn * NHW + gj * NW + gi;
    sidx[tid] = idx;
    __syncthreads();

    const int nv = s_nv[b];
    const bool valid = t < nv;

    // last-valid-write-wins ownership, branch-free accumulate
    int dup = 0;
    for (int t2 = t + 1; t2 < nv; t2++)
        dup |= (sidx[b * TT + t2] == idx);
    const bool owner = valid && !dup;

    g_tA[tid] = make_float4(gx - 0.5f * gw, gx + 0.5f * gw,
                            gy - 0.5f * gh, gy + 0.5f * gh);
    g_bz[tid] = 0.6f * area;
    g_m0[tid] = make_float4(gx, gy, gw, gh);
    g_lr[tid] = lr;
    g_meta[tid] = make_int4(idx, bn, owner ? 1 : 0, (int)tcls);
    if (t == 0) g_nv[b] = nv;
}

// ---------------------------------------------------------------------------
// Kernel 1 (R12 dense/sparse logic; epilogue = fence-free global accumulate,
// last block writes the final scalar). grid = (61, 16), block = 384.
// ---------------------------------------------------------------------------
__global__ void __launch_bounds__(TPB)
dense_kernel(const float* __restrict__ out, float* __restrict__ res)
{
    __shared__ float4 sA[TT + 4];
    __shared__ float  sbz[TT + 4];
    __shared__ int    smask[2];
    __shared__ int    s_nv;
    __shared__ float  wsum[TPB / 32];
    __shared__ double wsumd[TPB / 32];

    const int b = blockIdx.y;
    const int bx = blockIdx.x;
    const int tid = threadIdx.x;

    if (bx == DENSE_BX) {
        // =================== SPARSE PATH (R12 verbatim) ===================
        if (tid == 0) s_nv = g_nv[b];
        if (tid < TT) {
            sA[tid] = g_tA[b * TT + tid];
            sbz[tid] = g_bz[b * TT + tid];
        }
        __syncthreads();
        const int nv = s_nv;

        double c = 0.0;
        if (tid < TT) {
            const int4 meta = g_meta[b * TT + tid];
            if (meta.z) {
                const int idx = meta.x, bn = meta.y, cls = meta.w;
                const int hw = idx - bn * NHW;
                const int gj = hw / NW;
                const int gi = hw - gj * NW;
                const float4 m0 = g_m0[b * TT + tid];
                const float gx = m0.x, gy = m0.y, gw = m0.z, gh = m0.w;
                const float lr = g_lr[b * TT + tid];

                const float* op = out + ((b * NA + bn) * 8) * NHW + hw;
                const float o0 = op[0];
                const float o1 = op[NHW];
                const float o2 = op[2 * NHW];
                const float o3 = op[3 * NHW];
                const float o4 = op[4 * NHW];
                const float o5 = op[5 * NHW];
                const float o6 = op[6 * NHW];
                const float o7 = op[7 * NHW];

                const float x = sigmoidf_(o0);
                const float y = sigmoidf_(o1);
                const float px = x + (float)gi;
                const float py = y + (float)gj;
                const float pw = __expf(o2) * c_aw[bn];
                const float ph = __expf(o3) * c_ah[bn];

                const float tx = gx - (float)gi;
                const float ty = gy - (float)gj;
                const float tw = __logf(gw / c_aw[bn]);
                const float th = __logf(gh / c_ah[bn]);

                const float xlo = px - 0.5f * pw, xhi = px + 0.5f * pw;
                const float ylo = py - 0.5f * ph, yhi = py + 0.5f * ph;

                // tconf = IoU(gt, pred_at)
                const float iw = fminf(gx + 0.5f * gw, xhi) - fmaxf(gx - 0.5f * gw, xlo);
                const float ih = fminf(gy + 0.5f * gh, yhi) - fmaxf(gy - 0.5f * gh, ylo);
                const float ca = (iw > 0.f && ih > 0.f) ? iw * ih : 0.f;
                const float tconf = ca / (gw * gh + pw * ph - ca);

                const float conf = sigmoidf_(o4);

                // over predicate — IDENTICAL branch-free expression to dense path
                const float c1 = 0.6f * (pw * ph);
                float bestm = -1.f;
                for (int k = 0; k < nv; k++) {
                    const float4 a4 = sA[k];
                    const float iw2 = fminf(xhi, a4.y) - fmaxf(xlo, a4.x);
                    const float ih2 = fminf(yhi, a4.w) - fmaxf(ylo, a4.z);
                    const float hit = fminf(fminf(iw2, ih2),
                                            fmaf(1.6f, iw2 * ih2, -sbz[k]) - c1);
                    bestm = fmaxf(bestm, hit);
                }
                const bool over = bestm > 0.f;

                const float dx = x - tx;   c += 0.5 * (double)(dx * dx);
                const float dy = y - ty;   c += 0.5 * (double)(dy * dy);
                const float dw = o2 - tw;  c += 0.5 * (double)(dw * dw);
                const float dh = o3 - th;  c += 0.5 * (double)(dh * dh);
                const float dc = conf - tconf;
                c += 2.5 * (double)(dc * dc);                 // 0.5 * OBJECT_SCALE
                if (!over) c -= (double)(0.5f * conf * conf); // cancel dense term

                const float m = fmaxf(o5, o6);
                const float lse = m + __logf(__expf(o5 - m) + __expf(o6 - m));
                c += (double)(lse - (cls == 0 ? o5 : o6));

                const float clr = sigmoidf_(o7);
                const float dl = clr - lr;
                c += 0.25 * (double)(dl * dl);
            }
        }
#pragma unroll
        for (int off = 16; off > 0; off >>= 1)
            c += __shfl_down_sync(0xffffffffu, c, off);
        if ((tid & 31) == 0) wsumd[tid >> 5] = c;
        __syncthreads();
        if (tid == 0) {
            double s = 0.0;
#pragma unroll
            for (int k = 0; k < TPB / 32; k++) s += wsumd[k];
            accumulate_and_maybe_finalize(s, res);
        }
        return;
    }

    // =================== DENSE PATH (R12 verbatim): 2 cells/thread ===================
    const int a = bx / ROWGRP;
    const int j0 = (bx - a * ROWGRP) * ROWS;
    const int jr = tid / NW;          // 0..3
    const int i = tid - jr * NW;
    const int jA = j0 + jr;
    const int jB = j0 + jr + 4;

    // issue both cells' output loads early
    const float* base = out + ((b * NA + a) * 8) * NHW + i;
    const float* opA = base + jA * NW;
    const float* opB = base + jB * NW;
    const float a0 = opA[0];
    const float a1 = opA[NHW];
    const float a2 = opA[2 * NHW];
    const float a3 = opA[3 * NHW];
    const float a4v = opA[4 * NHW];
    const float b0 = opB[0];
    const float b1 = opB[NHW];
    const float b2 = opB[2 * NHW];
    const float b3 = opB[3 * NHW];
    const float b4v = opB[4 * NHW];

    if (tid == 0) s_nv = g_nv[b];

    // coalesced load of precomputed boxes + tight band prune + ballot compaction
    float4 ext; float bz = 0.f;
    bool keep = false;
    if (tid < TT) {
        ext = g_tA[b * TT + tid];
        bz = g_bz[b * TT + tid];
        // tight band (proof in R11): hit requires py strictly in (gylo, gyhi)
        keep = ((float)j0 < ext.w + 0.125f) && ((float)(j0 + ROWS) > ext.z - 0.125f);
    }
    __syncthreads();                      // s_nv visible
    if (tid < 64) {
        keep = keep && (tid < s_nv);
        unsigned m = __ballot_sync(0xffffffffu, keep);
        if ((tid & 31) == 0) smask[tid >> 5] = (int)m;
    }
    __syncthreads();
    const unsigned m0 = (unsigned)smask[0];
    const unsigned m1 = (unsigned)smask[1];
    const int cnt = __popc(m0) + __popc(m1);
    if (keep) {
        const unsigned below = (tid < 32) ? (m0 & ((1u << tid) - 1u))
                                          : m1 & ((tid == 32) ? 0u : ((1u << (tid - 32)) - 1u));
        const int pos = ((tid < 32) ? 0 : __popc(m0)) + __popc(below);
        sA[pos] = ext;
        sbz[pos] = bz;
    }
    if (tid < 4) {   // never-firing pad so the chunk-4 loop needs no tail
        sA[cnt + tid] = make_float4(1e30f, -1e30f, 1e30f, -1e30f);
        sbz[cnt + tid] = 0.f;
    }
    __syncthreads();

    // cell A box
    const float pxA = sigmoidf_(a0) + (float)i;
    const float pyA = sigmoidf_(a1) + (float)jA;
    const float pwA = __expf(a2) * c_aw[a];
    const float phA = __expf(a3) * c_ah[a];
    const float xloA = pxA - 0.5f * pwA, xhiA = pxA + 0.5f * pwA;
    const float yloA = pyA - 0.5f * phA, yhiA = pyA + 0.5f * phA;
    const float c1A = 0.6f * (pwA * phA);
    // cell B box
    const float pxB = sigmoidf_(b0) + (float)i;
    const float pyB = sigmoidf_(b1) + (float)jB;
    const float pwB = __expf(b2) * c_aw[a];
    const float phB = __expf(b3) * c_ah[a];
    const float xloB = pxB - 0.5f * pwB, xhiB = pxB + 0.5f * pwB;
    const float yloB = pyB - 0.5f * phB, yhiB = pyB + 0.5f * phB;
    const float c1B = 0.6f * (pwB * phB);

    // branch-free inner loop, two independent accumulation chains
    float bestA = -1.f, bestB = -1.f;
    for (int k = 0; k < cnt; k += 4) {
#pragma unroll
        for (int u = 0; u < 4; u++) {
            const float4 a4 = sA[k + u];
            const float z = sbz[k + u];
            const float iwA = fminf(xhiA, a4.y) - fmaxf(xloA, a4.x);
            const float ihA = fminf(yhiA, a4.w) - fmaxf(yloA, a4.z);
            bestA = fmaxf(bestA, fminf(fminf(iwA, ihA),
                                       fmaf(1.6f, iwA * ihA, -z) - c1A));
            const float iwB = fminf(xhiB, a4.y) - fmaxf(xloB, a4.x);
            const float ihB = fminf(yhiB, a4.w) - fmaxf(yloB, a4.z);
            bestB = fmaxf(bestB, fminf(fminf(iwB, ihB),
                                       fmaf(1.6f, iwB * ihB, -z) - c1B));
        }
    }

    const float confA = sigmoidf_(a4v);
    const float confB = sigmoidf_(b4v);
    float term = (bestA > 0.f ? 0.f : 0.5f * confA * confA)
               + (bestB > 0.f ? 0.f : 0.5f * confB * confB);

#pragma unroll
    for (int off = 16; off > 0; off >>= 1)
        term += __shfl_down_sync(0xffffffffu, term, off);
    if ((tid & 31) == 0) wsum[tid >> 5] = term;
    __syncthreads();
    if (tid == 0) {
        float s = 0.f;
#pragma unroll
        for (int k = 0; k < TPB / 32; k++) s += wsum[k];
        accumulate_and_maybe_finalize((double)s, res);
    }
}

extern "C" void kernel_launch(void* const* d_in, const int* in_sizes, int n_in,
                              void* d_out, int out_size)
{
    const float* output = (const float*)d_in[0];
    const float* target = (const float*)d_in[1];
    float* res = (float*)d_out;

    box_prep<<<1, NB * TT>>>(target);
    dense_kernel<<<dim3(DENSE_BX + 1, NB), TPB>>>(output, res);
}